// round 2
// baseline (speedup 1.0000x reference)
#include <cuda_runtime.h>
#include <cuda_bf16.h>
#include <math.h>

// Problem constants (match reference)
#define N_NODES  100000
#define N_EDGES  3200000
#define IN_CH    128
#define HID_CH   128
#define OUT_CH   64
#define N_GRAPHS 128

// ---------------- scratch (device globals; no allocation allowed) ----------------
__device__ float g_deg[N_NODES];
__device__ float g_dinv[N_NODES];
__device__ int   g_cnt[N_NODES];
__device__ int   g_ptr[N_NODES + 1];
__device__ int   g_cursor[N_NODES];
__device__ int   g_bsum[128];
__device__ int   g_boff[128];
__device__ int2  g_csr[N_EDGES];                 // {src, __float_as_int(norm)}
__device__ float g_xw[N_NODES * HID_CH];         // X @ W (pre-aggregation)
__device__ float g_h[N_NODES * HID_CH];          // post-aggregation activations
__device__ float g_pool[N_GRAPHS * HID_CH];
__device__ int   g_is64;                         // 1 if index tensors are int64

// index accessor: buffer may be int32 or int64 depending on JAX x64 config
__device__ __forceinline__ int load_idx(const void* p, long long i, int is64) {
    if (is64) return (int)((const long long*)p)[i];
    return ((const int*)p)[i];
}

// ---------------- dtype probe ----------------
// If data is int64 (values < 2^31, nonneg), every upper 32-bit word is 0.
// If data is int32 (random node ids), upper words are the next indices — ~never all zero.
__global__ void k_detect(const int* p) {
    if (threadIdx.x == 0 && blockIdx.x == 0) {
        int nz = 0;
        for (int i = 0; i < 64; i++) nz |= p[2 * i + 1];
        g_is64 = (nz == 0) ? 1 : 0;
    }
}

// ---------------- init ----------------
__global__ void k_zero() {
    int i = blockIdx.x * blockDim.x + threadIdx.x;
    if (i < N_NODES) { g_deg[i] = 0.f; g_cnt[i] = 0; }
    if (i < N_GRAPHS * HID_CH) g_pool[i] = 0.f;
}

// ---------------- pass 1: degree + per-target edge counts ----------------
__global__ void k_pass1(const void* __restrict__ ei, const float* __restrict__ w) {
    int e = blockIdx.x * blockDim.x + threadIdx.x;
    if (e >= N_EDGES) return;
    int is64 = g_is64;
    int c = load_idx(ei, (long long)N_EDGES + e, is64);
    atomicAdd(&g_deg[c], w[e]);
    atomicAdd(&g_cnt[c], 1);
}

__global__ void k_dinv() {
    int i = blockIdx.x * blockDim.x + threadIdx.x;
    if (i >= N_NODES) return;
    // self-loop weight 1.0 added to degree; always > 0
    g_dinv[i] = rsqrtf(g_deg[i] + 1.0f);
}

// ---------------- exclusive scan of counts -> g_ptr ----------------
__global__ void k_scan1(int n) {
    __shared__ int sm[1024];
    int i = blockIdx.x * 1024 + threadIdx.x;
    int v = (i < n) ? g_cnt[i] : 0;
    sm[threadIdx.x] = v;
    __syncthreads();
    for (int off = 1; off < 1024; off <<= 1) {
        int t = (threadIdx.x >= off) ? sm[threadIdx.x - off] : 0;
        __syncthreads();
        sm[threadIdx.x] += t;
        __syncthreads();
    }
    if (i < n) g_ptr[i + 1] = sm[threadIdx.x];   // inclusive scan shifted by 1
    if (threadIdx.x == 1023) g_bsum[blockIdx.x] = sm[1023];
}

__global__ void k_scan2(int nb) {
    if (threadIdx.x == 0 && blockIdx.x == 0) {
        int acc = 0;
        for (int b = 0; b < nb; b++) { int t = g_bsum[b]; g_boff[b] = acc; acc += t; }
    }
}

__global__ void k_scan3(int n) {
    int i = blockIdx.x * blockDim.x + threadIdx.x;
    if (i == 0) g_ptr[0] = 0;
    if (i < n) g_ptr[i + 1] += g_boff[i >> 10];
}

// cursor needs final ptr values; do it after scan3 completes
__global__ void k_cursor(int n) {
    int i = blockIdx.x * blockDim.x + threadIdx.x;
    if (i < n) g_cursor[i] = g_ptr[i];
}

// ---------------- pass 2: fill CSR with (src, norm) ----------------
__global__ void k_fill(const void* __restrict__ ei, const float* __restrict__ w) {
    int e = blockIdx.x * blockDim.x + threadIdx.x;
    if (e >= N_EDGES) return;
    int is64 = g_is64;
    int r = load_idx(ei, e, is64);
    int c = load_idx(ei, (long long)N_EDGES + e, is64);
    int p = atomicAdd(&g_cursor[c], 1);
    float nrm = g_dinv[r] * w[e] * g_dinv[c];
    g_csr[p] = make_int2(r, __float_as_int(nrm));
}

// ---------------- GEMM: C[M,128] = A[M,128] @ W[128,128] ----------------
// Block tile 64x128, full K=128 resident in smem. 256 threads, 4x8 micro-tile.
#define AS_STRIDE 132
__global__ void k_gemm128(const float* __restrict__ A, const float* __restrict__ W,
                          float* __restrict__ C, int M) {
    extern __shared__ float sm[];
    float* As = sm;                       // 64 x AS_STRIDE
    float* Ws = sm + 64 * AS_STRIDE;      // 128 x 128
    int tid = threadIdx.x;
    int row0 = blockIdx.x * 64;

    // load W (16384 floats)
    for (int i = tid; i < 128 * 128 / 4; i += 256)
        ((float4*)Ws)[i] = ((const float4*)W)[i];

    // load A tile: thread (k4 = tid&31, r = tid>>5), rows strided by 8
    int k4 = tid & 31, rr = tid >> 5;
    for (int r = rr; r < 64; r += 8) {
        int gr = row0 + r;
        float4 v = make_float4(0.f, 0.f, 0.f, 0.f);
        if (gr < M) v = ((const float4*)(A + (size_t)gr * 128))[k4];
        ((float4*)(As + r * AS_STRIDE))[k4] = v;
    }
    __syncthreads();

    int tc = tid & 15;      // col group: cols tc*8 .. tc*8+7
    int tr = tid >> 4;      // row group: rows tr*4 .. tr*4+3
    float acc[4][8];
    #pragma unroll
    for (int i = 0; i < 4; i++)
        #pragma unroll
        for (int j = 0; j < 8; j++) acc[i][j] = 0.f;

    #pragma unroll 4
    for (int k = 0; k < 128; k++) {
        float a0 = As[(tr * 4 + 0) * AS_STRIDE + k];
        float a1 = As[(tr * 4 + 1) * AS_STRIDE + k];
        float a2 = As[(tr * 4 + 2) * AS_STRIDE + k];
        float a3 = As[(tr * 4 + 3) * AS_STRIDE + k];
        float4 b0 = *(const float4*)&Ws[k * 128 + tc * 8];
        float4 b1 = *(const float4*)&Ws[k * 128 + tc * 8 + 4];
        float bv[8] = {b0.x, b0.y, b0.z, b0.w, b1.x, b1.y, b1.z, b1.w};
        float av[4] = {a0, a1, a2, a3};
        #pragma unroll
        for (int i = 0; i < 4; i++)
            #pragma unroll
            for (int j = 0; j < 8; j++)
                acc[i][j] = fmaf(av[i], bv[j], acc[i][j]);
    }

    #pragma unroll
    for (int i = 0; i < 4; i++) {
        int gr = row0 + tr * 4 + i;
        if (gr < M) {
            float4 o0 = make_float4(acc[i][0], acc[i][1], acc[i][2], acc[i][3]);
            float4 o1 = make_float4(acc[i][4], acc[i][5], acc[i][6], acc[i][7]);
            ((float4*)(C + (size_t)gr * 128))[tc * 2 + 0] = o0;
            ((float4*)(C + (size_t)gr * 128))[tc * 2 + 1] = o1;
        }
    }
}

// ---------------- aggregation: warp per node, float4 per lane ----------------
__global__ void k_agg(const float* __restrict__ xw, const float* __restrict__ bias,
                      float* __restrict__ out) {
    int gwarp = (blockIdx.x * blockDim.x + threadIdx.x) >> 5;
    if (gwarp >= N_NODES) return;
    int lane = threadIdx.x & 31;
    int beg = g_ptr[gwarp], end = g_ptr[gwarp + 1];

    float4 acc = make_float4(0.f, 0.f, 0.f, 0.f);
    for (int e = beg; e < end; e += 32) {
        int n = min(32, end - e);
        int2 ed = (lane < n) ? g_csr[e + lane] : make_int2(0, 0);
        for (int j = 0; j < n; j++) {
            int src   = __shfl_sync(0xffffffffu, ed.x, j);
            float nrm = __int_as_float(__shfl_sync(0xffffffffu, ed.y, j));
            float4 v = *(const float4*)&xw[(size_t)src * 128 + lane * 4];
            acc.x = fmaf(v.x, nrm, acc.x);
            acc.y = fmaf(v.y, nrm, acc.y);
            acc.z = fmaf(v.z, nrm, acc.z);
            acc.w = fmaf(v.w, nrm, acc.w);
        }
    }
    // self loop: weight dinv[i]^2
    float di = g_dinv[gwarp];
    float s = di * di;
    float4 v = *(const float4*)&xw[(size_t)gwarp * 128 + lane * 4];
    acc.x = fmaf(v.x, s, acc.x);
    acc.y = fmaf(v.y, s, acc.y);
    acc.z = fmaf(v.z, s, acc.z);
    acc.w = fmaf(v.w, s, acc.w);

    float4 b = *(const float4*)&bias[lane * 4];
    float4 o;
    o.x = fmaxf(acc.x + b.x, 0.f);
    o.y = fmaxf(acc.y + b.y, 0.f);
    o.z = fmaxf(acc.z + b.z, 0.f);
    o.w = fmaxf(acc.w + b.w, 0.f);
    *(float4*)&out[(size_t)gwarp * 128 + lane * 4] = o;
}

// ---------------- pooling: segment_sum over sorted batch ----------------
#define POOL_NB 512
__global__ void k_pool(const float* __restrict__ h, const void* __restrict__ batch) {
    int c = threadIdx.x;   // 128 threads = 128 channels
    int start = blockIdx.x * POOL_NB;
    if (start >= N_NODES) return;
    int is64 = g_is64;
    int end = min(start + POOL_NB, N_NODES);
    int cur = load_idx(batch, start, is64);
    float acc = 0.f;
    for (int n = start; n < end; n++) {
        int g = load_idx(batch, n, is64);
        if (g != cur) {
            atomicAdd(&g_pool[cur * HID_CH + c], acc);
            acc = 0.f; cur = g;
        }
        acc += h[(size_t)n * 128 + c];
    }
    atomicAdd(&g_pool[cur * HID_CH + c], acc);
}

// ---------------- classifier + sigmoid ----------------
__global__ void k_final(const float* __restrict__ Wc, const float* __restrict__ bc,
                        float* __restrict__ out) {
    int g = blockIdx.x;      // 128 graphs
    int c = threadIdx.x;     // 64 outputs
    float s = bc[c];
    #pragma unroll 4
    for (int k = 0; k < 128; k++)
        s = fmaf(g_pool[g * 128 + k], Wc[k * 64 + c], s);
    out[g * 64 + c] = 1.f / (1.f + expf(-s));
}

// ---------------- launch ----------------
extern "C" void kernel_launch(void* const* d_in, const int* in_sizes, int n_in,
                              void* d_out, int out_size) {
    const float* x     = (const float*)d_in[0];
    const void*  ei    = d_in[1];               // int32 or int64, probed on device
    const float* ew    = (const float*)d_in[2];
    const void*  batch = d_in[3];
    const float* W1    = (const float*)d_in[4];
    const float* b1    = (const float*)d_in[5];
    const float* W2    = (const float*)d_in[6];
    const float* b2    = (const float*)d_in[7];
    const float* Wc    = (const float*)d_in[8];
    const float* bc    = (const float*)d_in[9];
    float* out = (float*)d_out;

    const int gemm_smem = (64 * AS_STRIDE + 128 * 128) * (int)sizeof(float);
    cudaFuncSetAttribute(k_gemm128, cudaFuncAttributeMaxDynamicSharedMemorySize, gemm_smem);

    float* d_xw; cudaGetSymbolAddress((void**)&d_xw, g_xw);
    float* d_h;  cudaGetSymbolAddress((void**)&d_h,  g_h);

    const int TB = 256;
    const int egrid = (N_EDGES + TB - 1) / TB;
    const int ngrid = (N_NODES + TB - 1) / TB;
    const int nb_scan = (N_NODES + 1023) / 1024;

    // dtype probe + init + CSR build
    k_detect<<<1, 32>>>((const int*)ei);
    k_zero<<<ngrid, TB>>>();
    k_pass1<<<egrid, TB>>>(ei, ew);
    k_dinv<<<ngrid, TB>>>();
    k_scan1<<<nb_scan, 1024>>>(N_NODES);
    k_scan2<<<1, 32>>>(nb_scan);
    k_scan3<<<ngrid, TB>>>(N_NODES);
    k_cursor<<<ngrid, TB>>>(N_NODES);
    k_fill<<<egrid, TB>>>(ei, ew);

    const int gemm_grid = (N_NODES + 63) / 64;
    const int agg_grid = (N_NODES * 32 + TB - 1) / TB;  // warp per node

    // layer 1
    k_gemm128<<<gemm_grid, 256, gemm_smem>>>(x, W1, d_xw, N_NODES);
    k_agg<<<agg_grid, TB>>>(d_xw, b1, d_h);
    // layer 2
    k_gemm128<<<gemm_grid, 256, gemm_smem>>>(d_h, W2, d_xw, N_NODES);
    k_agg<<<agg_grid, TB>>>(d_xw, b2, d_h);

    // pooling + classifier
    const int pool_grid = (N_NODES + POOL_NB - 1) / POOL_NB;
    k_pool<<<pool_grid, 128>>>(d_h, batch);
    k_final<<<N_GRAPHS, OUT_CH>>>(Wc, bc, out);

    (void)in_sizes; (void)n_in; (void)out_size;
}

// round 4
// speedup vs baseline: 1.2006x; 1.2006x over previous
#include <cuda_runtime.h>
#include <cuda_bf16.h>
#include <math.h>
#include <stdint.h>

// Problem constants (match reference)
#define N_NODES  100000
#define N_EDGES  3200000
#define IN_CH    128
#define HID_CH   128
#define OUT_CH   64
#define N_GRAPHS 128

// ---------------- scratch (device globals; no allocation allowed) ----------------
__device__ float g_deg[N_NODES];
__device__ float g_dinv[N_NODES];
__device__ int   g_cnt[N_NODES];
__device__ int   g_ptr[N_NODES + 1];
__device__ int   g_cursor[N_NODES];
__device__ int   g_bsum[128];
__device__ int   g_boff[128];
__device__ int2  g_csr[N_EDGES];                 // {src, __float_as_int(norm)}
__device__ float g_xw[N_NODES * HID_CH];         // X @ W (pre-aggregation)
__device__ float g_h[N_NODES * HID_CH];          // post-aggregation activations
__device__ float g_pool[N_GRAPHS * HID_CH];
__device__ int   g_is64;                         // 1 if index tensors are int64
// bf16-split transposed weights: wt[n*128+k] = W[k*128+n]
__device__ __nv_bfloat16 g_w1hi[HID_CH * IN_CH];
__device__ __nv_bfloat16 g_w1lo[HID_CH * IN_CH];
__device__ __nv_bfloat16 g_w2hi[HID_CH * HID_CH];
__device__ __nv_bfloat16 g_w2lo[HID_CH * HID_CH];

__device__ __forceinline__ uint32_t smem_u32(const void* p) {
    uint32_t a;
    asm("{ .reg .u64 t; cvta.to.shared.u64 t, %1; cvt.u32.u64 %0, t; }" : "=r"(a) : "l"(p));
    return a;
}

// ---------------- index accessor (int32 or int64) ----------------
__device__ __forceinline__ int load_idx(const void* p, long long i, int is64) {
    if (is64) return (int)((const long long*)p)[i];
    return ((const int*)p)[i];
}

__global__ void k_detect(const int* p) {
    if (threadIdx.x == 0 && blockIdx.x == 0) {
        int nz = 0;
        for (int i = 0; i < 64; i++) nz |= p[2 * i + 1];
        g_is64 = (nz == 0) ? 1 : 0;
    }
}

// ---------------- weight transpose + bf16 split ----------------
__global__ void k_wsplit(const float* __restrict__ W, __nv_bfloat16* __restrict__ hi,
                         __nv_bfloat16* __restrict__ lo) {
    int i = blockIdx.x * blockDim.x + threadIdx.x;   // i = k*128 + n
    if (i >= 128 * 128) return;
    int k = i >> 7, n = i & 127;
    float w = W[i];
    __nv_bfloat16 h = __float2bfloat16_rn(w);
    __nv_bfloat16 l = __float2bfloat16_rn(w - __bfloat162float(h));
    hi[n * 128 + k] = h;
    lo[n * 128 + k] = l;
}

// ---------------- init ----------------
__global__ void k_zero() {
    int i = blockIdx.x * blockDim.x + threadIdx.x;
    if (i < N_NODES) { g_deg[i] = 0.f; g_cnt[i] = 0; }
    if (i < N_GRAPHS * HID_CH) g_pool[i] = 0.f;
}

// ---------------- pass 1: degree + per-target edge counts ----------------
__global__ void k_pass1(const void* __restrict__ ei, const float* __restrict__ w) {
    int e = blockIdx.x * blockDim.x + threadIdx.x;
    if (e >= N_EDGES) return;
    int is64 = g_is64;
    int c = load_idx(ei, (long long)N_EDGES + e, is64);
    atomicAdd(&g_deg[c], w[e]);
    atomicAdd(&g_cnt[c], 1);
}

__global__ void k_dinv() {
    int i = blockIdx.x * blockDim.x + threadIdx.x;
    if (i >= N_NODES) return;
    g_dinv[i] = rsqrtf(g_deg[i] + 1.0f);
}

// ---------------- exclusive scan of counts -> g_ptr ----------------
__global__ void k_scan1(int n) {
    __shared__ int sm[1024];
    int i = blockIdx.x * 1024 + threadIdx.x;
    int v = (i < n) ? g_cnt[i] : 0;
    sm[threadIdx.x] = v;
    __syncthreads();
    for (int off = 1; off < 1024; off <<= 1) {
        int t = (threadIdx.x >= off) ? sm[threadIdx.x - off] : 0;
        __syncthreads();
        sm[threadIdx.x] += t;
        __syncthreads();
    }
    if (i < n) g_ptr[i + 1] = sm[threadIdx.x];
    if (threadIdx.x == 1023) g_bsum[blockIdx.x] = sm[1023];
}

__global__ void k_scan2(int nb) {
    if (threadIdx.x == 0 && blockIdx.x == 0) {
        int acc = 0;
        for (int b = 0; b < nb; b++) { int t = g_bsum[b]; g_boff[b] = acc; acc += t; }
    }
}

__global__ void k_scan3(int n) {
    int i = blockIdx.x * blockDim.x + threadIdx.x;
    if (i == 0) g_ptr[0] = 0;
    if (i < n) g_ptr[i + 1] += g_boff[i >> 10];
}

__global__ void k_cursor(int n) {
    int i = blockIdx.x * blockDim.x + threadIdx.x;
    if (i < n) g_cursor[i] = g_ptr[i];
}

// ---------------- pass 2: fill CSR with (src, norm) ----------------
__global__ void k_fill(const void* __restrict__ ei, const float* __restrict__ w) {
    int e = blockIdx.x * blockDim.x + threadIdx.x;
    if (e >= N_EDGES) return;
    int is64 = g_is64;
    int r = load_idx(ei, e, is64);
    int c = load_idx(ei, (long long)N_EDGES + e, is64);
    int p = atomicAdd(&g_cursor[c], 1);
    float nrm = g_dinv[r] * w[e] * g_dinv[c];
    g_csr[p] = make_int2(r, __float_as_int(nrm));
}

// ---------------- mma.sync GEMM: C[M,128] = A[M,128] @ W[128,128] (3x bf16 split) ----------------
// Block = 128 rows x 128 cols, 256 threads (8 warps). Warp w: rows w*16..w*16+15, all 128 cols.
// smem: Ah, Al, Bh, Bl each [128][PADK] bf16 (PADK=136 -> row stride 272B = 68 words == 4 mod 32).
#define PADK 136
#define SME_TOTAL (4 * 128 * PADK * 2)

__global__ __launch_bounds__(256, 1) void k_gemm_tc(const float* __restrict__ A,
                                                    const __nv_bfloat16* __restrict__ wt_hi,
                                                    const __nv_bfloat16* __restrict__ wt_lo,
                                                    float* __restrict__ C, int M) {
    extern __shared__ char smem_raw[];
    __nv_bfloat16* Ah = (__nv_bfloat16*)smem_raw;
    __nv_bfloat16* Al = Ah + 128 * PADK;
    __nv_bfloat16* Bh = Al + 128 * PADK;
    __nv_bfloat16* Bl = Bh + 128 * PADK;
    int tid = threadIdx.x;
    int wid = tid >> 5, lane = tid & 31;
    int row0 = blockIdx.x * 128;

    // Load A [128x128 f32] -> hi/lo bf16 split
    for (int g = tid; g < 128 * 32; g += 256) {
        int r = g >> 5, c4 = (g & 31) * 4;
        int gr = row0 + r;
        float4 v = make_float4(0.f, 0.f, 0.f, 0.f);
        if (gr < M) v = ((const float4*)(A + (size_t)gr * 128))[c4 >> 2];
        __nv_bfloat16 h0 = __float2bfloat16_rn(v.x), h1 = __float2bfloat16_rn(v.y);
        __nv_bfloat16 h2 = __float2bfloat16_rn(v.z), h3 = __float2bfloat16_rn(v.w);
        __nv_bfloat16* ah = Ah + r * PADK + c4;
        __nv_bfloat16* al = Al + r * PADK + c4;
        ah[0] = h0; ah[1] = h1; ah[2] = h2; ah[3] = h3;
        al[0] = __float2bfloat16_rn(v.x - __bfloat162float(h0));
        al[1] = __float2bfloat16_rn(v.y - __bfloat162float(h1));
        al[2] = __float2bfloat16_rn(v.z - __bfloat162float(h2));
        al[3] = __float2bfloat16_rn(v.w - __bfloat162float(h3));
    }
    // Load B (pre-split transposed weights): 16-byte vectors
    for (int g = tid; g < 128 * 16; g += 256) {
        int r = g >> 4, c8 = (g & 15) * 8;
        *(float4*)(Bh + r * PADK + c8) = *(const float4*)(wt_hi + r * 128 + c8);
        *(float4*)(Bl + r * PADK + c8) = *(const float4*)(wt_lo + r * 128 + c8);
    }
    __syncthreads();

    float acc[16][4];
    #pragma unroll
    for (int nt = 0; nt < 16; nt++)
        #pragma unroll
        for (int j = 0; j < 4; j++) acc[nt][j] = 0.f;

    int rowA = wid * 16;
    // A frag address: row = rowA + lane%16, col base = (lane/16)*8 within k-chunk
    int a_r = rowA + (lane & 15);
    int a_c = (lane >> 4) * 8;
    // B frag address (x2, lanes 0-15 used): n row = nt*8 + lane%8, k base = ((lane>>3)&1)*8
    int b_r = (lane & 7);
    int b_c = ((lane >> 3) & 1) * 8;

    const __nv_bfloat16* Aptr[3] = {Ah, Ah, Al};
    const __nv_bfloat16* Bptr[3] = {Bh, Bl, Bh};

    #pragma unroll
    for (int pass = 0; pass < 3; pass++) {
        uint32_t abase = smem_u32(Aptr[pass] + a_r * PADK + a_c);
        uint32_t bbase = smem_u32(Bptr[pass] + b_r * PADK + b_c);
        #pragma unroll
        for (int kc = 0; kc < 8; kc++) {
            uint32_t a0, a1, a2, a3;
            asm volatile("ldmatrix.sync.aligned.m8n8.x4.shared.b16 {%0,%1,%2,%3}, [%4];"
                         : "=r"(a0), "=r"(a1), "=r"(a2), "=r"(a3)
                         : "r"(abase + kc * 32));
            #pragma unroll
            for (int nt = 0; nt < 16; nt++) {
                uint32_t b0, b1;
                asm volatile("ldmatrix.sync.aligned.m8n8.x2.shared.b16 {%0,%1}, [%2];"
                             : "=r"(b0), "=r"(b1)
                             : "r"(bbase + (uint32_t)(nt * 8 * PADK * 2) + kc * 32));
                asm volatile("mma.sync.aligned.m16n8k16.row.col.f32.bf16.bf16.f32 "
                             "{%0,%1,%2,%3}, {%4,%5,%6,%7}, {%8,%9}, {%0,%1,%2,%3};"
                             : "+f"(acc[nt][0]), "+f"(acc[nt][1]), "+f"(acc[nt][2]), "+f"(acc[nt][3])
                             : "r"(a0), "r"(a1), "r"(a2), "r"(a3), "r"(b0), "r"(b1));
            }
        }
    }

    // Epilogue: thread t -> rows rowA + t/4 and rowA + t/4 + 8; cols nt*8 + (t%4)*2
    int er0 = row0 + rowA + (lane >> 2);
    int ec = (lane & 3) * 2;
    #pragma unroll
    for (int nt = 0; nt < 16; nt++) {
        if (er0 < M)
            *(float2*)(C + (size_t)er0 * 128 + nt * 8 + ec) = make_float2(acc[nt][0], acc[nt][1]);
        if (er0 + 8 < M)
            *(float2*)(C + (size_t)(er0 + 8) * 128 + nt * 8 + ec) = make_float2(acc[nt][2], acc[nt][3]);
    }
}

// ---------------- aggregation: warp per node, float4 per lane ----------------
__global__ void k_agg(const float* __restrict__ xw, const float* __restrict__ bias,
                      float* __restrict__ out) {
    int gwarp = (blockIdx.x * blockDim.x + threadIdx.x) >> 5;
    if (gwarp >= N_NODES) return;
    int lane = threadIdx.x & 31;
    int beg = g_ptr[gwarp], end = g_ptr[gwarp + 1];

    float4 acc = make_float4(0.f, 0.f, 0.f, 0.f);
    for (int e = beg; e < end; e += 32) {
        int n = min(32, end - e);
        int2 ed = (lane < n) ? g_csr[e + lane] : make_int2(0, 0);
        for (int j = 0; j < n; j++) {
            int src   = __shfl_sync(0xffffffffu, ed.x, j);
            float nrm = __int_as_float(__shfl_sync(0xffffffffu, ed.y, j));
            float4 v = *(const float4*)&xw[(size_t)src * 128 + lane * 4];
            acc.x = fmaf(v.x, nrm, acc.x);
            acc.y = fmaf(v.y, nrm, acc.y);
            acc.z = fmaf(v.z, nrm, acc.z);
            acc.w = fmaf(v.w, nrm, acc.w);
        }
    }
    float di = g_dinv[gwarp];
    float s = di * di;
    float4 v = *(const float4*)&xw[(size_t)gwarp * 128 + lane * 4];
    acc.x = fmaf(v.x, s, acc.x);
    acc.y = fmaf(v.y, s, acc.y);
    acc.z = fmaf(v.z, s, acc.z);
    acc.w = fmaf(v.w, s, acc.w);

    float4 b = *(const float4*)&bias[lane * 4];
    float4 o;
    o.x = fmaxf(acc.x + b.x, 0.f);
    o.y = fmaxf(acc.y + b.y, 0.f);
    o.z = fmaxf(acc.z + b.z, 0.f);
    o.w = fmaxf(acc.w + b.w, 0.f);
    *(float4*)&out[(size_t)gwarp * 128 + lane * 4] = o;
}

// ---------------- pooling: segment_sum over sorted batch ----------------
#define POOL_NB 512
__global__ void k_pool(const float* __restrict__ h, const void* __restrict__ batch) {
    int c = threadIdx.x;
    int start = blockIdx.x * POOL_NB;
    if (start >= N_NODES) return;
    int is64 = g_is64;
    int end = min(start + POOL_NB, N_NODES);
    int cur = load_idx(batch, start, is64);
    float acc = 0.f;
    for (int n = start; n < end; n++) {
        int g = load_idx(batch, n, is64);
        if (g != cur) {
            atomicAdd(&g_pool[cur * HID_CH + c], acc);
            acc = 0.f; cur = g;
        }
        acc += h[(size_t)n * 128 + c];
    }
    atomicAdd(&g_pool[cur * HID_CH + c], acc);
}

// ---------------- classifier + sigmoid ----------------
__global__ void k_final(const float* __restrict__ Wc, const float* __restrict__ bc,
                        float* __restrict__ out) {
    int g = blockIdx.x;
    int c = threadIdx.x;
    float s = bc[c];
    #pragma unroll 4
    for (int k = 0; k < 128; k++)
        s = fmaf(g_pool[g * 128 + k], Wc[k * 64 + c], s);
    out[g * 64 + c] = 1.f / (1.f + expf(-s));
}

// ---------------- launch ----------------
extern "C" void kernel_launch(void* const* d_in, const int* in_sizes, int n_in,
                              void* d_out, int out_size) {
    const float* x     = (const float*)d_in[0];
    const void*  ei    = d_in[1];
    const float* ew    = (const float*)d_in[2];
    const void*  batch = d_in[3];
    const float* W1    = (const float*)d_in[4];
    const float* b1    = (const float*)d_in[5];
    const float* W2    = (const float*)d_in[6];
    const float* b2    = (const float*)d_in[7];
    const float* Wc    = (const float*)d_in[8];
    const float* bc    = (const float*)d_in[9];
    float* out = (float*)d_out;

    cudaFuncSetAttribute(k_gemm_tc, cudaFuncAttributeMaxDynamicSharedMemorySize, SME_TOTAL);

    float* d_xw; cudaGetSymbolAddress((void**)&d_xw, g_xw);
    float* d_h;  cudaGetSymbolAddress((void**)&d_h,  g_h);
    __nv_bfloat16 *d_w1hi, *d_w1lo, *d_w2hi, *d_w2lo;
    cudaGetSymbolAddress((void**)&d_w1hi, g_w1hi);
    cudaGetSymbolAddress((void**)&d_w1lo, g_w1lo);
    cudaGetSymbolAddress((void**)&d_w2hi, g_w2hi);
    cudaGetSymbolAddress((void**)&d_w2lo, g_w2lo);

    const int TB = 256;
    const int egrid = (N_EDGES + TB - 1) / TB;
    const int ngrid = (N_NODES + TB - 1) / TB;
    const int nb_scan = (N_NODES + 1023) / 1024;

    // dtype probe + weight split + init + CSR build
    k_detect<<<1, 32>>>((const int*)ei);
    k_wsplit<<<64, 256>>>(W1, d_w1hi, d_w1lo);
    k_wsplit<<<64, 256>>>(W2, d_w2hi, d_w2lo);
    k_zero<<<ngrid, TB>>>();
    k_pass1<<<egrid, TB>>>(ei, ew);
    k_dinv<<<ngrid, TB>>>();
    k_scan1<<<nb_scan, 1024>>>(N_NODES);
    k_scan2<<<1, 32>>>(nb_scan);
    k_scan3<<<ngrid, TB>>>(N_NODES);
    k_cursor<<<ngrid, TB>>>(N_NODES);
    k_fill<<<egrid, TB>>>(ei, ew);

    const int mma_grid = (N_NODES + 127) / 128;
    const int agg_grid = (N_NODES * 32 + TB - 1) / TB;

    // layer 1
    k_gemm_tc<<<mma_grid, 256, SME_TOTAL>>>(x, d_w1hi, d_w1lo, d_xw, N_NODES);
    k_agg<<<agg_grid, TB>>>(d_xw, b1, d_h);
    // layer 2
    k_gemm_tc<<<mma_grid, 256, SME_TOTAL>>>(d_h, d_w2hi, d_w2lo, d_xw, N_NODES);
    k_agg<<<agg_grid, TB>>>(d_xw, b2, d_h);

    // pooling + classifier
    const int pool_grid = (N_NODES + POOL_NB - 1) / POOL_NB;
    k_pool<<<pool_grid, 128>>>(d_h, batch);
    k_final<<<N_GRAPHS, OUT_CH>>>(Wc, bc, out);

    (void)in_sizes; (void)n_in; (void)out_size;
}

// round 5
// speedup vs baseline: 1.3393x; 1.1155x over previous
#include <cuda_runtime.h>
#include <cuda_bf16.h>
#include <cuda_fp16.h>
#include <math.h>
#include <stdint.h>

// Problem constants (match reference)
#define N_NODES  100000
#define N_EDGES  3200000
#define IN_CH    128
#define HID_CH   128
#define OUT_CH   64
#define N_GRAPHS 128

// ---------------- scratch (device globals; no allocation allowed) ----------------
__device__ float g_deg[N_NODES];
__device__ float g_dinv[N_NODES];
__device__ int   g_cnt[N_NODES];
__device__ int   g_ptr[N_NODES + 1];
__device__ int   g_cursor[N_NODES];
__device__ int   g_bsum[128];
__device__ int   g_boff[128];
__device__ int2  g_csr[N_EDGES];                 // {src, __float_as_int(raw edge weight)}
__device__ __half g_y16[N_NODES * HID_CH];       // dinv-prescaled GEMM output (gather operand)
__device__ float g_h[N_NODES * HID_CH];          // post-aggregation activations (fp32)
__device__ float g_pool[N_GRAPHS * HID_CH];
__device__ int   g_is64;                         // 1 if index tensors are int64
// bf16-split transposed weights: wt[n*128+k] = W[k*128+n]
__device__ __nv_bfloat16 g_w1hi[HID_CH * IN_CH];
__device__ __nv_bfloat16 g_w1lo[HID_CH * IN_CH];
__device__ __nv_bfloat16 g_w2hi[HID_CH * HID_CH];
__device__ __nv_bfloat16 g_w2lo[HID_CH * HID_CH];

__device__ __forceinline__ uint32_t smem_u32(const void* p) {
    uint32_t a;
    asm("{ .reg .u64 t; cvta.to.shared.u64 t, %1; cvt.u32.u64 %0, t; }" : "=r"(a) : "l"(p));
    return a;
}

// ---------------- index accessor (int32 or int64) ----------------
__device__ __forceinline__ int load_idx(const void* p, long long i, int is64) {
    if (is64) return (int)((const long long*)p)[i];
    return ((const int*)p)[i];
}

__global__ void k_detect(const int* p) {
    if (threadIdx.x == 0 && blockIdx.x == 0) {
        int nz = 0;
        for (int i = 0; i < 64; i++) nz |= p[2 * i + 1];
        g_is64 = (nz == 0) ? 1 : 0;
    }
}

// ---------------- weight transpose + bf16 split ----------------
__global__ void k_wsplit(const float* __restrict__ W, __nv_bfloat16* __restrict__ hi,
                         __nv_bfloat16* __restrict__ lo) {
    int i = blockIdx.x * blockDim.x + threadIdx.x;   // i = k*128 + n
    if (i >= 128 * 128) return;
    int k = i >> 7, n = i & 127;
    float w = W[i];
    __nv_bfloat16 h = __float2bfloat16_rn(w);
    __nv_bfloat16 l = __float2bfloat16_rn(w - __bfloat162float(h));
    hi[n * 128 + k] = h;
    lo[n * 128 + k] = l;
}

// ---------------- init ----------------
__global__ void k_zero() {
    int i = blockIdx.x * blockDim.x + threadIdx.x;
    if (i < N_NODES) { g_deg[i] = 0.f; g_cnt[i] = 0; }
    if (i < N_GRAPHS * HID_CH) g_pool[i] = 0.f;
}

// ---------------- pass 1: degree + per-target edge counts ----------------
__global__ void k_pass1(const void* __restrict__ ei, const float* __restrict__ w) {
    int e = blockIdx.x * blockDim.x + threadIdx.x;
    if (e >= N_EDGES) return;
    int is64 = g_is64;
    int c = load_idx(ei, (long long)N_EDGES + e, is64);
    atomicAdd(&g_deg[c], w[e]);
    atomicAdd(&g_cnt[c], 1);
}

__global__ void k_dinv() {
    int i = blockIdx.x * blockDim.x + threadIdx.x;
    if (i >= N_NODES) return;
    g_dinv[i] = rsqrtf(g_deg[i] + 1.0f);
}

// ---------------- exclusive scan of counts -> g_ptr ----------------
__global__ void k_scan1(int n) {
    __shared__ int sm[1024];
    int i = blockIdx.x * 1024 + threadIdx.x;
    int v = (i < n) ? g_cnt[i] : 0;
    sm[threadIdx.x] = v;
    __syncthreads();
    for (int off = 1; off < 1024; off <<= 1) {
        int t = (threadIdx.x >= off) ? sm[threadIdx.x - off] : 0;
        __syncthreads();
        sm[threadIdx.x] += t;
        __syncthreads();
    }
    if (i < n) g_ptr[i + 1] = sm[threadIdx.x];
    if (threadIdx.x == 1023) g_bsum[blockIdx.x] = sm[1023];
}

__global__ void k_scan2(int nb) {
    if (threadIdx.x == 0 && blockIdx.x == 0) {
        int acc = 0;
        for (int b = 0; b < nb; b++) { int t = g_bsum[b]; g_boff[b] = acc; acc += t; }
    }
}

__global__ void k_scan3(int n) {
    int i = blockIdx.x * blockDim.x + threadIdx.x;
    if (i == 0) g_ptr[0] = 0;
    if (i < n) g_ptr[i + 1] += g_boff[i >> 10];
}

__global__ void k_cursor(int n) {
    int i = blockIdx.x * blockDim.x + threadIdx.x;
    if (i < n) g_cursor[i] = g_ptr[i];
}

// ---------------- pass 2: fill CSR with (src, raw weight) — no random reads ----------------
__global__ void k_fill(const void* __restrict__ ei, const float* __restrict__ w) {
    int e = blockIdx.x * blockDim.x + threadIdx.x;
    if (e >= N_EDGES) return;
    int is64 = g_is64;
    int r = load_idx(ei, e, is64);
    int c = load_idx(ei, (long long)N_EDGES + e, is64);
    int p = atomicAdd(&g_cursor[c], 1);
    g_csr[p] = make_int2(r, __float_as_int(w[e]));
}

// ---------------- mma.sync GEMM: Y[M,128] = fp16(dinv .* (A[M,128] @ W)) (3x bf16 split) ----------------
// Block = 128 rows x 128 cols, 256 threads (8 warps). Warp w: rows w*16..w*16+15, all 128 cols.
// smem: Ah, Al, Bh, Bl each [128][PADK] bf16 (PADK=136 -> row stride 272B = 68 words == 4 mod 32).
#define PADK 136
#define SME_TOTAL (4 * 128 * PADK * 2)

__global__ __launch_bounds__(256, 1) void k_gemm_tc(const float* __restrict__ A,
                                                    const __nv_bfloat16* __restrict__ wt_hi,
                                                    const __nv_bfloat16* __restrict__ wt_lo,
                                                    __half* __restrict__ Y, int M) {
    extern __shared__ char smem_raw[];
    __nv_bfloat16* Ah = (__nv_bfloat16*)smem_raw;
    __nv_bfloat16* Al = Ah + 128 * PADK;
    __nv_bfloat16* Bh = Al + 128 * PADK;
    __nv_bfloat16* Bl = Bh + 128 * PADK;
    int tid = threadIdx.x;
    int wid = tid >> 5, lane = tid & 31;
    int row0 = blockIdx.x * 128;

    // Load A [128x128 f32] -> hi/lo bf16 split
    for (int g = tid; g < 128 * 32; g += 256) {
        int r = g >> 5, c4 = (g & 31) * 4;
        int gr = row0 + r;
        float4 v = make_float4(0.f, 0.f, 0.f, 0.f);
        if (gr < M) v = ((const float4*)(A + (size_t)gr * 128))[c4 >> 2];
        __nv_bfloat16 h0 = __float2bfloat16_rn(v.x), h1 = __float2bfloat16_rn(v.y);
        __nv_bfloat16 h2 = __float2bfloat16_rn(v.z), h3 = __float2bfloat16_rn(v.w);
        __nv_bfloat16* ah = Ah + r * PADK + c4;
        __nv_bfloat16* al = Al + r * PADK + c4;
        ah[0] = h0; ah[1] = h1; ah[2] = h2; ah[3] = h3;
        al[0] = __float2bfloat16_rn(v.x - __bfloat162float(h0));
        al[1] = __float2bfloat16_rn(v.y - __bfloat162float(h1));
        al[2] = __float2bfloat16_rn(v.z - __bfloat162float(h2));
        al[3] = __float2bfloat16_rn(v.w - __bfloat162float(h3));
    }
    // Load B (pre-split transposed weights): 16-byte vectors
    for (int g = tid; g < 128 * 16; g += 256) {
        int r = g >> 4, c8 = (g & 15) * 8;
        *(float4*)(Bh + r * PADK + c8) = *(const float4*)(wt_hi + r * 128 + c8);
        *(float4*)(Bl + r * PADK + c8) = *(const float4*)(wt_lo + r * 128 + c8);
    }
    __syncthreads();

    float acc[16][4];
    #pragma unroll
    for (int nt = 0; nt < 16; nt++)
        #pragma unroll
        for (int j = 0; j < 4; j++) acc[nt][j] = 0.f;

    int rowA = wid * 16;
    int a_r = rowA + (lane & 15);
    int a_c = (lane >> 4) * 8;
    int b_r = (lane & 7);
    int b_c = ((lane >> 3) & 1) * 8;

    const __nv_bfloat16* Aptr[3] = {Ah, Ah, Al};
    const __nv_bfloat16* Bptr[3] = {Bh, Bl, Bh};

    #pragma unroll
    for (int pass = 0; pass < 3; pass++) {
        uint32_t abase = smem_u32(Aptr[pass] + a_r * PADK + a_c);
        uint32_t bbase = smem_u32(Bptr[pass] + b_r * PADK + b_c);
        #pragma unroll
        for (int kc = 0; kc < 8; kc++) {
            uint32_t a0, a1, a2, a3;
            asm volatile("ldmatrix.sync.aligned.m8n8.x4.shared.b16 {%0,%1,%2,%3}, [%4];"
                         : "=r"(a0), "=r"(a1), "=r"(a2), "=r"(a3)
                         : "r"(abase + kc * 32));
            #pragma unroll
            for (int nt = 0; nt < 16; nt++) {
                uint32_t b0, b1;
                asm volatile("ldmatrix.sync.aligned.m8n8.x2.shared.b16 {%0,%1}, [%2];"
                             : "=r"(b0), "=r"(b1)
                             : "r"(bbase + (uint32_t)(nt * 8 * PADK * 2) + kc * 32));
                asm volatile("mma.sync.aligned.m16n8k16.row.col.f32.bf16.bf16.f32 "
                             "{%0,%1,%2,%3}, {%4,%5,%6,%7}, {%8,%9}, {%0,%1,%2,%3};"
                             : "+f"(acc[nt][0]), "+f"(acc[nt][1]), "+f"(acc[nt][2]), "+f"(acc[nt][3])
                             : "r"(a0), "r"(a1), "r"(a2), "r"(a3), "r"(b0), "r"(b1));
            }
        }
    }

    // Epilogue: scale by dinv[row], pack to fp16.
    int er0 = row0 + rowA + (lane >> 2);
    int er1 = er0 + 8;
    int ec = (lane & 3) * 2;
    float d0 = (er0 < M) ? g_dinv[er0] : 0.f;
    float d1 = (er1 < M) ? g_dinv[er1] : 0.f;
    #pragma unroll
    for (int nt = 0; nt < 16; nt++) {
        if (er0 < M)
            *(__half2*)(Y + (size_t)er0 * 128 + nt * 8 + ec) =
                __floats2half2_rn(acc[nt][0] * d0, acc[nt][1] * d0);
        if (er1 < M)
            *(__half2*)(Y + (size_t)er1 * 128 + nt * 8 + ec) =
                __floats2half2_rn(acc[nt][2] * d1, acc[nt][3] * d1);
    }
}

// ---------------- aggregation: warp per node, lane owns 4 channels (fp16 gather) ----------------
__global__ void k_agg(const __half* __restrict__ y, const float* __restrict__ bias,
                      float* __restrict__ out) {
    int gwarp = (blockIdx.x * blockDim.x + threadIdx.x) >> 5;
    if (gwarp >= N_NODES) return;
    int lane = threadIdx.x & 31;
    int ch = lane * 4;
    int beg = g_ptr[gwarp], end = g_ptr[gwarp + 1];

    float a0 = 0.f, a1 = 0.f, a2 = 0.f, a3 = 0.f;
    for (int e = beg; e < end; e += 32) {
        int n = min(32, end - e);
        int2 ed = (lane < n) ? g_csr[e + lane] : make_int2(0, 0);
        int j = 0;
        for (; j + 1 < n; j += 2) {
            int   s0 = __shfl_sync(0xffffffffu, ed.x, j);
            float w0 = __int_as_float(__shfl_sync(0xffffffffu, ed.y, j));
            int   s1 = __shfl_sync(0xffffffffu, ed.x, j + 1);
            float w1 = __int_as_float(__shfl_sync(0xffffffffu, ed.y, j + 1));
            float2 r0 = *(const float2*)(y + (size_t)s0 * 128 + ch);
            float2 r1 = *(const float2*)(y + (size_t)s1 * 128 + ch);
            float2 p0 = __half22float2(*(__half2*)&r0.x);
            float2 p1 = __half22float2(*(__half2*)&r0.y);
            float2 q0 = __half22float2(*(__half2*)&r1.x);
            float2 q1 = __half22float2(*(__half2*)&r1.y);
            a0 = fmaf(p0.x, w0, a0); a1 = fmaf(p0.y, w0, a1);
            a2 = fmaf(p1.x, w0, a2); a3 = fmaf(p1.y, w0, a3);
            a0 = fmaf(q0.x, w1, a0); a1 = fmaf(q0.y, w1, a1);
            a2 = fmaf(q1.x, w1, a2); a3 = fmaf(q1.y, w1, a3);
        }
        if (j < n) {
            int   s0 = __shfl_sync(0xffffffffu, ed.x, j);
            float w0 = __int_as_float(__shfl_sync(0xffffffffu, ed.y, j));
            float2 r0 = *(const float2*)(y + (size_t)s0 * 128 + ch);
            float2 p0 = __half22float2(*(__half2*)&r0.x);
            float2 p1 = __half22float2(*(__half2*)&r0.y);
            a0 = fmaf(p0.x, w0, a0); a1 = fmaf(p0.y, w0, a1);
            a2 = fmaf(p1.x, w0, a2); a3 = fmaf(p1.y, w0, a3);
        }
    }
    // self loop: +y_i (weight 1 in prescaled space)
    {
        float2 r0 = *(const float2*)(y + (size_t)gwarp * 128 + ch);
        float2 p0 = __half22float2(*(__half2*)&r0.x);
        float2 p1 = __half22float2(*(__half2*)&r0.y);
        a0 += p0.x; a1 += p0.y; a2 += p1.x; a3 += p1.y;
    }
    float di = g_dinv[gwarp];
    float4 b = *(const float4*)(bias + ch);
    float4 o;
    o.x = fmaxf(fmaf(di, a0, b.x), 0.f);
    o.y = fmaxf(fmaf(di, a1, b.y), 0.f);
    o.z = fmaxf(fmaf(di, a2, b.z), 0.f);
    o.w = fmaxf(fmaf(di, a3, b.w), 0.f);
    *(float4*)(out + (size_t)gwarp * 128 + ch) = o;
}

// ---------------- pooling: segment_sum over sorted batch ----------------
#define POOL_NB 512
__global__ void k_pool(const float* __restrict__ h, const void* __restrict__ batch) {
    int c = threadIdx.x;
    int start = blockIdx.x * POOL_NB;
    if (start >= N_NODES) return;
    int is64 = g_is64;
    int end = min(start + POOL_NB, N_NODES);
    int cur = load_idx(batch, start, is64);
    float acc = 0.f;
    for (int n = start; n < end; n++) {
        int g = load_idx(batch, n, is64);
        if (g != cur) {
            atomicAdd(&g_pool[cur * HID_CH + c], acc);
            acc = 0.f; cur = g;
        }
        acc += h[(size_t)n * 128 + c];
    }
    atomicAdd(&g_pool[cur * HID_CH + c], acc);
}

// ---------------- classifier + sigmoid ----------------
__global__ void k_final(const float* __restrict__ Wc, const float* __restrict__ bc,
                        float* __restrict__ out) {
    int g = blockIdx.x;
    int c = threadIdx.x;
    float s = bc[c];
    #pragma unroll 4
    for (int k = 0; k < 128; k++)
        s = fmaf(g_pool[g * 128 + k], Wc[k * 64 + c], s);
    out[g * 64 + c] = 1.f / (1.f + expf(-s));
}

// ---------------- launch ----------------
extern "C" void kernel_launch(void* const* d_in, const int* in_sizes, int n_in,
                              void* d_out, int out_size) {
    const float* x     = (const float*)d_in[0];
    const void*  ei    = d_in[1];
    const float* ew    = (const float*)d_in[2];
    const void*  batch = d_in[3];
    const float* W1    = (const float*)d_in[4];
    const float* b1    = (const float*)d_in[5];
    const float* W2    = (const float*)d_in[6];
    const float* b2    = (const float*)d_in[7];
    const float* Wc    = (const float*)d_in[8];
    const float* bc    = (const float*)d_in[9];
    float* out = (float*)d_out;

    cudaFuncSetAttribute(k_gemm_tc, cudaFuncAttributeMaxDynamicSharedMemorySize, SME_TOTAL);

    __half* d_y; cudaGetSymbolAddress((void**)&d_y, g_y16);
    float* d_h;  cudaGetSymbolAddress((void**)&d_h,  g_h);
    __nv_bfloat16 *d_w1hi, *d_w1lo, *d_w2hi, *d_w2lo;
    cudaGetSymbolAddress((void**)&d_w1hi, g_w1hi);
    cudaGetSymbolAddress((void**)&d_w1lo, g_w1lo);
    cudaGetSymbolAddress((void**)&d_w2hi, g_w2hi);
    cudaGetSymbolAddress((void**)&d_w2lo, g_w2lo);

    const int TB = 256;
    const int egrid = (N_EDGES + TB - 1) / TB;
    const int ngrid = (N_NODES + TB - 1) / TB;
    const int nb_scan = (N_NODES + 1023) / 1024;

    // dtype probe + weight split + init + CSR build
    k_detect<<<1, 32>>>((const int*)ei);
    k_wsplit<<<64, 256>>>(W1, d_w1hi, d_w1lo);
    k_wsplit<<<64, 256>>>(W2, d_w2hi, d_w2lo);
    k_zero<<<ngrid, TB>>>();
    k_pass1<<<egrid, TB>>>(ei, ew);
    k_dinv<<<ngrid, TB>>>();
    k_scan1<<<nb_scan, 1024>>>(N_NODES);
    k_scan2<<<1, 32>>>(nb_scan);
    k_scan3<<<ngrid, TB>>>(N_NODES);
    k_cursor<<<ngrid, TB>>>(N_NODES);
    k_fill<<<egrid, TB>>>(ei, ew);

    const int mma_grid = (N_NODES + 127) / 128;
    const int agg_grid = (N_NODES * 32 + TB - 1) / TB;

    // layer 1
    k_gemm_tc<<<mma_grid, 256, SME_TOTAL>>>(x, d_w1hi, d_w1lo, d_y, N_NODES);
    k_agg<<<agg_grid, TB>>>(d_y, b1, d_h);
    // layer 2
    k_gemm_tc<<<mma_grid, 256, SME_TOTAL>>>(d_h, d_w2hi, d_w2lo, d_y, N_NODES);
    k_agg<<<agg_grid, TB>>>(d_y, b2, d_h);

    // pooling + classifier
    const int pool_grid = (N_NODES + POOL_NB - 1) / POOL_NB;
    k_pool<<<pool_grid, 128>>>(d_h, batch);
    k_final<<<N_GRAPHS, OUT_CH>>>(Wc, bc, out);

    (void)in_sizes; (void)n_in; (void)out_size;
}